// round 7
// baseline (speedup 1.0000x reference)
#include <cuda_runtime.h>
#include <cuda_bf16.h>
#include <cstdint>

// out[b,h,i,j] = scores[b,h,i,j] + sum_d q[b,h,i,d] * emb[j-i+4096, d]
// Per 64(i) x 256(j) tile: G[64 x 320] = Q @ E_window^T, single-pass tf32
// mma.sync (m16n8k8), operands stored FRAGMENT-MAJOR in SMEM so every frag
// load is one aligned conflict-free LDS.128. Then skewed band add via SMEM.

#define S_LEN 2048
#define D_HEAD 64
#define TI 64
#define TJ 256
#define NB 320
#define HALF 4096
#define GS 333          // staging stride words: ==1 mod 4 -> aligned LDS.128

// A: 32 tiles (mf_g 0..3 x ks 0..7) x 132 words
#define TSA 132
#define OFF_A 0
// B: 160 pair-tiles (nfg 0..39 x kp 0..3) x 132 words
#define TSB 132
#define OFF_B 16896
#define SMEM_TOTAL 101376
// G staging 64 x GS x 4B = 85248 B reuses [0, SMEM_TOTAL) after GEMM.

static __device__ __forceinline__ uint32_t smem_u32(const void* p) {
    uint32_t a;
    asm("{ .reg .u64 t; cvta.to.shared.u64 t, %1; cvt.u32.u64 %0, t; }"
        : "=r"(a) : "l"(p));
    return a;
}
static __device__ __forceinline__ uint32_t to_tf32(float x) {
    uint32_t r;
    asm("cvt.rna.tf32.f32 %0, %1;" : "=r"(r) : "f"(x));
    return r;
}

__global__ __launch_bounds__(256, 2)
void relpos_tf32_kernel(const float* __restrict__ q,
                        const float* __restrict__ scores,
                        const float* __restrict__ emb,
                        float* __restrict__ out)
{
    extern __shared__ char smem[];
    const uint32_t sb = smem_u32(smem);
    const int tid = threadIdx.x, wid = tid >> 5, lane = tid & 31;
    const int bh = blockIdx.z, i0 = blockIdx.y * TI, j0 = blockIdx.x * TJ;

    // ---- Load Q [64 x 64] -> tf32 fragment-major SMEM ----
    // elem (row,k): tile=(row>>4)*8+(k>>3), lane_t=((row&7)<<2)|(k&3),
    // q-slot=((k>>2)&1)*2 + ((row>>3)&1); word = tile*TSA + lane_t*4 + slot
    {
        const float* qb = q + ((size_t)bh * S_LEN + i0) * D_HEAD;
        #pragma unroll
        for (int it = 0; it < 4; it++) {
            int u = it * 256 + tid;
            int row = u >> 4, g = u & 15;            // k = 4g..4g+3
            float4 v = __ldg((const float4*)(qb + (size_t)row * D_HEAD) + g);
            uint32_t tile = (uint32_t)((row >> 4) * 8 + (g >> 1));
            uint32_t base = sb + OFF_A +
                ((tile * TSA + (uint32_t)(((row & 7) << 2)) * 4
                  + (uint32_t)((g & 1) * 2 + ((row >> 3) & 1))) << 2);
            uint32_t t0 = to_tf32(v.x), t1 = to_tf32(v.y),
                     t2 = to_tf32(v.z), t3 = to_tf32(v.w);
            asm volatile("st.shared.b32 [%0], %1;" :: "r"(base),      "r"(t0) : "memory");
            asm volatile("st.shared.b32 [%0], %1;" :: "r"(base + 16), "r"(t1) : "memory");
            asm volatile("st.shared.b32 [%0], %1;" :: "r"(base + 32), "r"(t2) : "memory");
            asm volatile("st.shared.b32 [%0], %1;" :: "r"(base + 48), "r"(t3) : "memory");
        }
    }
    // ---- Load E window [320 x 64] -> tf32 fragment-major SMEM (B) ----
    // elem (n,k): pt=(n>>3)*4+(k>>4), lane_t=((n&7)<<2)|(k&3),
    // slot=((k>>3)&1)*2 + ((k>>2)&1); word = pt*TSB + lane_t*4 + slot
    {
        const int e0 = j0 - i0 + HALF - (TI - 1);    // [2049, 5825]; +319 in-bounds
        const float* eb = emb + (size_t)e0 * D_HEAD;
        #pragma unroll
        for (int it = 0; it < 20; it++) {
            int u = it * 256 + tid;
            int n = u >> 4, g = u & 15;              // k = 4g..4g+3
            float4 v = __ldg((const float4*)(eb + (size_t)n * D_HEAD) + g);
            uint32_t pt = (uint32_t)((n >> 3) * 4 + (g >> 2));
            uint32_t base = sb + OFF_B +
                ((pt * TSB + (uint32_t)(((n & 7) << 2)) * 4
                  + (uint32_t)(((g >> 1) & 1) * 2 + (g & 1))) << 2);
            uint32_t t0 = to_tf32(v.x), t1 = to_tf32(v.y),
                     t2 = to_tf32(v.z), t3 = to_tf32(v.w);
            asm volatile("st.shared.b32 [%0], %1;" :: "r"(base),      "r"(t0) : "memory");
            asm volatile("st.shared.b32 [%0], %1;" :: "r"(base + 16), "r"(t1) : "memory");
            asm volatile("st.shared.b32 [%0], %1;" :: "r"(base + 32), "r"(t2) : "memory");
            asm volatile("st.shared.b32 [%0], %1;" :: "r"(base + 48), "r"(t3) : "memory");
        }
    }
    __syncthreads();

    // ---- GEMM: warp (mg, nh) -> rows [32mg,+32) x cols [80nh,+80) ----
    const int mg = wid >> 2, nh = wid & 3;
    const int m0g = mg * 2;          // global 16-row frag index base
    const int nf0 = nh * 10;         // global 8-col frag index base
    float c[2][10][4];
    #pragma unroll
    for (int mf = 0; mf < 2; mf++)
        #pragma unroll
        for (int f = 0; f < 10; f++)
            #pragma unroll
            for (int k = 0; k < 4; k++) c[mf][f][k] = 0.0f;

    #pragma unroll
    for (int kp = 0; kp < 4; kp++) {
        // A frags: [ks parity][mf][4 regs], one LDS.128 each
        uint32_t a[2][2][4];
        #pragma unroll
        for (int e = 0; e < 2; e++)
            #pragma unroll
            for (int mf = 0; mf < 2; mf++) {
                uint32_t tile = (uint32_t)((m0g + mf) * 8 + 2 * kp + e);
                uint32_t addr = sb + OFF_A + ((tile * TSA + (uint32_t)lane * 4) << 2);
                asm volatile("ld.shared.v4.b32 {%0,%1,%2,%3}, [%4];"
                             : "=r"(a[e][mf][0]), "=r"(a[e][mf][1]),
                               "=r"(a[e][mf][2]), "=r"(a[e][mf][3])
                             : "r"(addr));
            }
        #pragma unroll
        for (int nf = 0; nf < 10; nf++) {
            uint32_t pt = (uint32_t)((nf0 + nf) * 4 + kp);
            uint32_t addr = sb + OFF_B + ((pt * TSB + (uint32_t)lane * 4) << 2);
            uint32_t b0, b1, b2, b3;     // (ks even: b0,b1) (ks odd: b2,b3)
            asm volatile("ld.shared.v4.b32 {%0,%1,%2,%3}, [%4];"
                         : "=r"(b0), "=r"(b1), "=r"(b2), "=r"(b3) : "r"(addr));
            #pragma unroll
            for (int mf = 0; mf < 2; mf++) {
                asm volatile("mma.sync.aligned.m16n8k8.row.col.f32.tf32.tf32.f32 "
                             "{%0,%1,%2,%3}, {%4,%5,%6,%7}, {%8,%9}, {%0,%1,%2,%3};"
                             : "+f"(c[mf][nf][0]), "+f"(c[mf][nf][1]),
                               "+f"(c[mf][nf][2]), "+f"(c[mf][nf][3])
                             : "r"(a[0][mf][0]), "r"(a[0][mf][1]),
                               "r"(a[0][mf][2]), "r"(a[0][mf][3]),
                               "r"(b0), "r"(b1));
                asm volatile("mma.sync.aligned.m16n8k8.row.col.f32.tf32.tf32.f32 "
                             "{%0,%1,%2,%3}, {%4,%5,%6,%7}, {%8,%9}, {%0,%1,%2,%3};"
                             : "+f"(c[mf][nf][0]), "+f"(c[mf][nf][1]),
                               "+f"(c[mf][nf][2]), "+f"(c[mf][nf][3])
                             : "r"(a[1][mf][0]), "r"(a[1][mf][1]),
                               "r"(a[1][mf][2]), "r"(a[1][mf][3]),
                               "r"(b2), "r"(b3));
            }
        }
    }
    __syncthreads();   // all GEMM reads done -> operand region reusable for G

    // ---- Stage G to skewed SMEM: word(row,col) = row*GS + 1 + col ----
    {
        const int m0 = mg * 32, n0 = nh * 80;
        #pragma unroll
        for (int mf = 0; mf < 2; mf++) {
            int r0 = m0 + mf * 16 + (lane >> 2);
            #pragma unroll
            for (int nf = 0; nf < 10; nf++) {
                int col = n0 + nf * 8 + 2 * (lane & 3);
                uint32_t w0 = sb + (uint32_t)((r0 * GS + 1 + col) << 2);
                uint32_t w1 = w0 + (uint32_t)(8 * GS * 4);
                asm volatile("st.shared.b32 [%0], %1;" :: "r"(w0),     "f"(c[mf][nf][0]) : "memory");
                asm volatile("st.shared.b32 [%0], %1;" :: "r"(w0 + 4), "f"(c[mf][nf][1]) : "memory");
                asm volatile("st.shared.b32 [%0], %1;" :: "r"(w1),     "f"(c[mf][nf][2]) : "memory");
                asm volatile("st.shared.b32 [%0], %1;" :: "r"(w1 + 4), "f"(c[mf][nf][3]) : "memory");
            }
        }
    }
    __syncthreads();

    // ---- Combine: out[row][jj] = scores[row][jj] + G[row][jj - row + 63] ----
    // staged word = row*(GS-1) + 64 + jj   (aligned float4: GS-1 % 4 == 0)
    {
        const float* Gw = (const float*)smem;
        const size_t srow = (size_t)bh * S_LEN + (size_t)i0;
        #pragma unroll
        for (int rr = 0; rr < 8; rr++) {
            int row = wid * 8 + rr;
            const float* gr = Gw + row * (GS - 1) + 64;
            size_t off = (srow + row) * S_LEN + (size_t)j0 + 4 * lane;
            #pragma unroll
            for (int h = 0; h < 2; h++) {
                int jj = h * 128 + 4 * lane;
                float4 s = __ldg((const float4*)(scores + off + h * 128));
                float4 g = *(const float4*)(gr + jj);
                float4 o = make_float4(s.x + g.x, s.y + g.y, s.z + g.z, s.w + g.w);
                *(float4*)(out + off + h * 128) = o;
            }
        }
    }
}

extern "C" void kernel_launch(void* const* d_in, const int* in_sizes, int n_in,
                              void* d_out, int out_size)
{
    const float* q      = (const float*)d_in[0];  // [2,16,2048,64]
    const float* scores = (const float*)d_in[1];  // [2,16,2048,2048]
    const float* emb    = (const float*)d_in[2];  // [8192,64]
    float* out = (float*)d_out;

    cudaFuncSetAttribute(relpos_tf32_kernel,
                         cudaFuncAttributeMaxDynamicSharedMemorySize, SMEM_TOTAL);
    dim3 grid(S_LEN / TJ, S_LEN / TI, 32);   // (8, 32, 32) = 8192 CTAs
    relpos_tf32_kernel<<<grid, 256, SMEM_TOTAL>>>(q, scores, emb, out);
}